// round 1
// baseline (speedup 1.0000x reference)
#include <cuda_runtime.h>
#include <math.h>

// Problem constants
#define NN   16384
#define EE   8192
#define DIM  256
#define CAP_R 128    // max hyperedges per node (E[deg]=41, max ~70)
#define CAP_C 192    // max nodes per hyperedge (E[deg]=82, max ~125)
#define LN_EPS 1e-5f

// ---------------- static device scratch (no allocations allowed) ------------
__device__ int   g_cols[NN * CAP_R];     // ELL-CSR: hyperedge ids per node
__device__ int   g_rows[EE * CAP_C];     // ELL-CSC: node ids per hyperedge
__device__ int   g_rcnt[NN];
__device__ int   g_ccnt[EE];
__device__ float g_invsv[NN];            // rsqrt(max(D_v,1))
__device__ float g_invse[EE];            // rsqrt(max(D_e,1))

__device__ float g_tmpE[EE * DIM];       // H_norm^T @ x0
__device__ float g_x1a [EE * DIM];       // x1 + tmpE@We + be
__device__ float g_msg [NN * DIM];       // H_norm @ x1a
__device__ float g_u   [NN * DIM];       // pre-LN1
__device__ float g_x0l [NN * DIM];       // x0_local
__device__ float g_x0g [NN * DIM];       // x0_global
__device__ float g_ret [EE * DIM];       // H_norm^T @ x0_local
__device__ float g_h   [NN * 2 * DIM];   // FFN hidden

// ---------------- sparse build ----------------------------------------------
__global__ void zero_ccnt_kernel() {
    int j = blockIdx.x * blockDim.x + threadIdx.x;
    if (j < EE) g_ccnt[j] = 0;
}

// One warp per node row: ordered ballot compaction (deterministic).
__global__ __launch_bounds__(256) void build_csr_kernel(const float* __restrict__ H) {
    int warp = (blockIdx.x * blockDim.x + threadIdx.x) >> 5;
    int lane = threadIdx.x & 31;
    if (warp >= NN) return;
    const float* row = H + (size_t)warp * EE;
    int base = 0;
    for (int it = 0; it < EE / 128; it++) {
        float4 v4 = *(const float4*)(row + it * 128 + lane * 4);
        float v[4] = {v4.x, v4.y, v4.z, v4.w};
#pragma unroll
        for (int j = 0; j < 4; j++) {
            unsigned m = __ballot_sync(0xffffffffu, v[j] != 0.0f);
            if (v[j] != 0.0f) {
                int pos = base + __popc(m & ((1u << lane) - 1u));
                if (pos < CAP_R) g_cols[warp * CAP_R + pos] = it * 128 + lane * 4 + j;
            }
            base += __popc(m);
        }
    }
    if (lane == 0) {
        g_rcnt[warp]  = min(base, CAP_R);
        g_invsv[warp] = rsqrtf(fmaxf((float)base, 1.0f));
    }
}

// Scatter CSR entries into per-hyperedge lists (order nondeterministic but
// value-set identical; only affects fp sum order at ~1e-7 rel).
__global__ void scatter_csc_kernel() {
    int tid = blockIdx.x * blockDim.x + threadIdx.x;
    int row = tid >> 7;          // /CAP_R
    int k   = tid & (CAP_R - 1);
    if (row >= NN) return;
    if (k < g_rcnt[row]) {
        int col = g_cols[row * CAP_R + k];
        int p = atomicAdd(&g_ccnt[col], 1);
        if (p < CAP_C) g_rows[col * CAP_C + p] = row;
    }
}

__global__ void finalize_cols_kernel() {
    int j = blockIdx.x * blockDim.x + threadIdx.x;
    if (j < EE) {
        int c = g_ccnt[j];
        g_invse[j] = rsqrtf(fmaxf((float)c, 1.0f));
        g_ccnt[j]  = min(c, CAP_C);
    }
}

// ---------------- SpMM gathers ----------------------------------------------
// out[e,:] = invse[e] * sum_{i in edge e} invsv[i] * src[i,:]
__global__ __launch_bounds__(DIM) void spmm_edges_kernel(const float* __restrict__ src,
                                                         float* __restrict__ out) {
    int e = blockIdx.x;
    int t = threadIdx.x;
    int cnt = g_ccnt[e];
    const int* lst = &g_rows[e * CAP_C];
    float a0 = 0.f, a1 = 0.f, a2 = 0.f, a3 = 0.f;
    int k = 0;
    for (; k + 4 <= cnt; k += 4) {
        int i0 = lst[k], i1 = lst[k+1], i2 = lst[k+2], i3 = lst[k+3];
        a0 = fmaf(src[(size_t)i0 * DIM + t], g_invsv[i0], a0);
        a1 = fmaf(src[(size_t)i1 * DIM + t], g_invsv[i1], a1);
        a2 = fmaf(src[(size_t)i2 * DIM + t], g_invsv[i2], a2);
        a3 = fmaf(src[(size_t)i3 * DIM + t], g_invsv[i3], a3);
    }
    for (; k < cnt; k++) {
        int i0 = lst[k];
        a0 = fmaf(src[(size_t)i0 * DIM + t], g_invsv[i0], a0);
    }
    out[(size_t)e * DIM + t] = ((a0 + a1) + (a2 + a3)) * g_invse[e];
}

// out[i,:] = invsv[i] * sum_{e in node i} invse[e] * src[e,:]
__global__ __launch_bounds__(DIM) void spmm_nodes_kernel(const float* __restrict__ src,
                                                         float* __restrict__ out) {
    int i = blockIdx.x;
    int t = threadIdx.x;
    int cnt = g_rcnt[i];
    const int* lst = &g_cols[i * CAP_R];
    float a0 = 0.f, a1 = 0.f, a2 = 0.f, a3 = 0.f;
    int k = 0;
    for (; k + 4 <= cnt; k += 4) {
        int e0 = lst[k], e1 = lst[k+1], e2 = lst[k+2], e3 = lst[k+3];
        a0 = fmaf(src[(size_t)e0 * DIM + t], g_invse[e0], a0);
        a1 = fmaf(src[(size_t)e1 * DIM + t], g_invse[e1], a1);
        a2 = fmaf(src[(size_t)e2 * DIM + t], g_invse[e2], a2);
        a3 = fmaf(src[(size_t)e3 * DIM + t], g_invse[e3], a3);
    }
    for (; k < cnt; k++) {
        int e0 = lst[k];
        a0 = fmaf(src[(size_t)e0 * DIM + t], g_invse[e0], a0);
    }
    out[(size_t)i * DIM + t] = ((a0 + a1) + (a2 + a3)) * g_invsv[i];
}

// ---------------- dense GEMM (fp32, 128x128x16, 8x8 micro-tile) -------------
// C[M,N] = epi( A[M,K] @ B[K,N] )
//   GELU=false: C = (RESID? resid : 0) + alpha * (AB + bias),  alpha = tanh(*gate) or 1
//   GELU=true : C = gelu_exact(AB + bias)
template<bool RESID, bool GELU>
__global__ __launch_bounds__(256) void gemm_kernel(
    const float* __restrict__ A, const float* __restrict__ B,
    const float* __restrict__ bias, const float* __restrict__ resid,
    const float* __restrict__ gate, float* __restrict__ C,
    int M, int N, int K)
{
    __shared__ float As[16][128];
    __shared__ float Bs[16][128];
    const int tid = threadIdx.x;
    const int m0 = blockIdx.y * 128;
    const int n0 = blockIdx.x * 128;
    const int tx = tid & 15;      // n micro-tile
    const int ty = tid >> 4;      // m micro-tile

    float acc[8][8];
#pragma unroll
    for (int i = 0; i < 8; i++)
#pragma unroll
        for (int j = 0; j < 8; j++) acc[i][j] = 0.0f;

    for (int k0 = 0; k0 < K; k0 += 16) {
#pragma unroll
        for (int p = 0; p < 2; p++) {
            int m  = (tid >> 2) + p * 64;
            int kk = (tid & 3) << 2;
            float4 v = *(const float4*)(A + (size_t)(m0 + m) * K + k0 + kk);
            As[kk + 0][m] = v.x; As[kk + 1][m] = v.y;
            As[kk + 2][m] = v.z; As[kk + 3][m] = v.w;
        }
#pragma unroll
        for (int p = 0; p < 2; p++) {
            int kk = (tid >> 5) + p * 8;
            int n  = (tid & 31) << 2;
            *(float4*)&Bs[kk][n] = *(const float4*)(B + (size_t)(k0 + kk) * N + n0 + n);
        }
        __syncthreads();
#pragma unroll
        for (int k = 0; k < 16; k++) {
            float a[8], b[8];
            *(float4*)(a)     = *(const float4*)&As[k][ty * 8];
            *(float4*)(a + 4) = *(const float4*)&As[k][ty * 8 + 4];
            *(float4*)(b)     = *(const float4*)&Bs[k][tx * 8];
            *(float4*)(b + 4) = *(const float4*)&Bs[k][tx * 8 + 4];
#pragma unroll
            for (int i = 0; i < 8; i++)
#pragma unroll
                for (int j = 0; j < 8; j++)
                    acc[i][j] = fmaf(a[i], b[j], acc[i][j]);
        }
        __syncthreads();
    }

    float alpha = 1.0f;
    if (!GELU && gate != nullptr) alpha = tanhf(gate[0]);

    float bv[8];
    *(float4*)(bv)     = *(const float4*)(bias + n0 + tx * 8);
    *(float4*)(bv + 4) = *(const float4*)(bias + n0 + tx * 8 + 4);

#pragma unroll
    for (int i = 0; i < 8; i++) {
        int row = m0 + ty * 8 + i;
        size_t base = (size_t)row * N + n0 + tx * 8;
        float o[8];
#pragma unroll
        for (int j = 0; j < 8; j++) {
            float v = acc[i][j] + bv[j];
            if (GELU) {
                v = 0.5f * v * (1.0f + erff(v * 0.7071067811865476f));
            } else {
                v *= alpha;
            }
            o[j] = v;
        }
        if (RESID) {
            float4 r0 = *(const float4*)(resid + base);
            float4 r1 = *(const float4*)(resid + base + 4);
            o[0] += r0.x; o[1] += r0.y; o[2] += r0.z; o[3] += r0.w;
            o[4] += r1.x; o[5] += r1.y; o[6] += r1.z; o[7] += r1.w;
        }
        *(float4*)(C + base)     = *(float4*)(o);
        *(float4*)(C + base + 4) = *(float4*)(o + 4);
    }
}

// ---------------- fused double LayerNorm (block per row, 256 threads) -------
__device__ __forceinline__ float block_sum_256(float v, float* sm) {
#pragma unroll
    for (int o = 16; o > 0; o >>= 1) v += __shfl_xor_sync(0xffffffffu, v, o);
    int w = threadIdx.x >> 5, lane = threadIdx.x & 31;
    if (lane == 0) sm[w] = v;
    __syncthreads();
    if (w == 0) {
        float s = (lane < 8) ? sm[lane] : 0.0f;
#pragma unroll
        for (int o = 4; o > 0; o >>= 1) s += __shfl_xor_sync(0xffffffffu, s, o);
        if (lane == 0) sm[0] = s;
    }
    __syncthreads();
    float r = sm[0];
    __syncthreads();
    return r;
}

__global__ __launch_bounds__(DIM) void ln_double_kernel(
    const float* __restrict__ g1, const float* __restrict__ b1,
    const float* __restrict__ g2, const float* __restrict__ b2)
{
    __shared__ float sm[8];
    int r = blockIdx.x, t = threadIdx.x;
    float v = g_u[(size_t)r * DIM + t];
    float mean = block_sum_256(v, sm) * (1.0f / DIM);
    float d = v - mean;
    float var = block_sum_256(d * d, sm) * (1.0f / DIM);
    float y = d * rsqrtf(var + LN_EPS) * g1[t] + b1[t];
    g_x0l[(size_t)r * DIM + t] = y;
    float m2 = block_sum_256(y, sm) * (1.0f / DIM);
    float d2 = y - m2;
    float v2 = block_sum_256(d2 * d2, sm) * (1.0f / DIM);
    g_x0g[(size_t)r * DIM + t] = d2 * rsqrtf(v2 + LN_EPS) * g2[t] + b2[t];
}

// ---------------- driver -----------------------------------------------------
extern "C" void kernel_launch(void* const* d_in, const int* in_sizes, int n_in,
                              void* d_out, int out_size) {
    const float* x0   = (const float*)d_in[0];
    const float* x1   = (const float*)d_in[1];
    const float* H    = (const float*)d_in[2];
    const float* Wn   = (const float*)d_in[3];
    const float* bn   = (const float*)d_in[4];
    const float* We   = (const float*)d_in[5];
    const float* be   = (const float*)d_in[6];
    const float* Wr   = (const float*)d_in[7];
    const float* br   = (const float*)d_in[8];
    const float* W1   = (const float*)d_in[9];
    const float* b1   = (const float*)d_in[10];
    const float* W2   = (const float*)d_in[11];
    const float* b2   = (const float*)d_in[12];
    const float* ln1g = (const float*)d_in[13];
    const float* ln1b = (const float*)d_in[14];
    const float* ln2g = (const float*)d_in[15];
    const float* ln2b = (const float*)d_in[16];
    const float* gl   = (const float*)d_in[17];
    const float* gr   = (const float*)d_in[18];

    float* out_x0 = (float*)d_out;                       // [NN, DIM]
    float* out_x1 = (float*)d_out + (size_t)NN * DIM;    // [EE, DIM]

    // device-symbol addresses for GEMM operands living in __device__ arrays
    float *p_tmpE, *p_x1a, *p_msg, *p_u, *p_x0l, *p_x0g, *p_ret, *p_h;
    cudaGetSymbolAddress((void**)&p_tmpE, g_tmpE);
    cudaGetSymbolAddress((void**)&p_x1a,  g_x1a);
    cudaGetSymbolAddress((void**)&p_msg,  g_msg);
    cudaGetSymbolAddress((void**)&p_u,    g_u);
    cudaGetSymbolAddress((void**)&p_x0l,  g_x0l);
    cudaGetSymbolAddress((void**)&p_x0g,  g_x0g);
    cudaGetSymbolAddress((void**)&p_ret,  g_ret);
    cudaGetSymbolAddress((void**)&p_h,    g_h);

    // 1) sparse structure build (one pass over the 536MB incidence matrix)
    zero_ccnt_kernel<<<EE / 256, 256>>>();
    build_csr_kernel<<<NN / 8, 256>>>(H);
    scatter_csc_kernel<<<(NN * CAP_R) / 256, 256>>>();
    finalize_cols_kernel<<<EE / 256, 256>>>();

    // 2) tmpE = H_norm^T @ x0
    spmm_edges_kernel<<<EE, DIM>>>(x0, p_tmpE);
    // 3) x1a = x1 + tmpE @ We + be
    gemm_kernel<true, false><<<dim3(DIM / 128, EE / 128), 256>>>(
        p_tmpE, We, be, x1, nullptr, p_x1a, EE, DIM, DIM);
    // 4) msg = H_norm @ x1a
    spmm_nodes_kernel<<<NN, DIM>>>(p_x1a, p_msg);
    // 5) u = x0 + tanh(gl) * (msg @ Wn + bn)
    gemm_kernel<true, false><<<dim3(DIM / 128, NN / 128), 256>>>(
        p_msg, Wn, bn, x0, gl, p_u, NN, DIM, DIM);
    // 6) x0_local = LN1(u); x0_global = LN2(x0_local)
    ln_double_kernel<<<NN, DIM>>>(ln1g, ln1b, ln2g, ln2b);
    // 7) ret = H_norm^T @ x0_local
    spmm_edges_kernel<<<EE, DIM>>>(p_x0l, p_ret);
    // 8) x1_out = x1a + tanh(gr) * (ret @ Wr + br)   -> second half of output
    gemm_kernel<true, false><<<dim3(DIM / 128, EE / 128), 256>>>(
        p_ret, Wr, br, p_x1a, gr, out_x1, EE, DIM, DIM);
    // 9) h = gelu(x0_global @ W1 + b1)
    gemm_kernel<false, true><<<dim3((2 * DIM) / 128, NN / 128), 256>>>(
        p_x0g, W1, b1, nullptr, nullptr, p_h, NN, 2 * DIM, DIM);
    // 10) x0_out = x0_global + h @ W2 + b2           -> first half of output
    gemm_kernel<true, false><<<dim3(DIM / 128, NN / 128), 256>>>(
        p_h, W2, b2, p_x0g, nullptr, out_x0, NN, DIM, 2 * DIM);

    (void)in_sizes; (void)n_in; (void)out_size;
}